// round 16
// baseline (speedup 1.0000x reference)
#include <cuda_runtime.h>
#include <cuda_fp16.h>
#include <math.h>
#include <stdint.h>

// ---------------- problem constants ----------------
constexpr int B_  = 2;
constexpr int N_  = 16;
constexpr int T_  = 512;
constexpr int D_  = 512;
constexpr int H_  = 8;
constexpr int DH_ = 64;
constexpr int FF_ = 828;
constexpr int FFP = 832;            // padded
constexpr int ROWS = B_ * N_ * T_;  // 16384

// ---------------- scratch ----------------
__device__ __align__(16) __half g_h   [(size_t)ROWS * D_];
__device__ float  g_gate[ROWS];
__device__ __align__(16) __half g_qkv [(size_t)3 * ROWS * D_];  // [which][b,n,h,t,dh]
__device__ __align__(16) __half g_attn[(size_t)ROWS * D_];      // [bn][t][512]
__device__ __align__(16) __half g_up  [(size_t)ROWS * FFP];     // zero-padded 828..831
__device__ float  g_poolp[B_ * N_ * 4 * D_];                    // [bn][ttile][512]
__device__ float  g_commit[B_ * N_];
__device__ float  g_hres[B_ * N_ * D_];
__device__ float  g_cs_c[B_ * N_ * 256];
__device__ float  g_cs_s[B_ * N_ * 256];
__device__ float  g_racc[B_ * N_ * N_];
__device__ float  g_fsig[B_ * N_ * D_];
// transposed half weights
__device__ __align__(16) __half g_wTall[(size_t)4 * N_ * D_ * D_];   // q,k,v,o : [n][out][k]
__device__ __align__(16) __half g_upT [(size_t)N_ * FF_ * D_];       // [n][828][512]
__device__ __align__(16) __half g_dnT [(size_t)N_ * D_ * FFP];       // [n][512][832]

// ---------------- helpers ----------------
__device__ __forceinline__ void mma_f16(float c[4], const uint32_t a[4],
                                        uint32_t b0, uint32_t b1)
{
    asm volatile(
        "mma.sync.aligned.m16n8k16.row.col.f32.f16.f16.f32 "
        "{%0,%1,%2,%3}, {%4,%5,%6,%7}, {%8,%9}, {%0,%1,%2,%3};"
        : "+f"(c[0]), "+f"(c[1]), "+f"(c[2]), "+f"(c[3])
        : "r"(a[0]), "r"(a[1]), "r"(a[2]), "r"(a[3]), "r"(b0), "r"(b1));
}
__device__ __forceinline__ void ldm4(uint32_t r[4], uint32_t addr) {
    asm volatile("ldmatrix.sync.aligned.m8n8.x4.shared.b16 {%0,%1,%2,%3}, [%4];"
        : "=r"(r[0]), "=r"(r[1]), "=r"(r[2]), "=r"(r[3]) : "r"(addr));
}
__device__ __forceinline__ void ldm4t(uint32_t r[4], uint32_t addr) {
    asm volatile("ldmatrix.sync.aligned.m8n8.x4.trans.shared.b16 {%0,%1,%2,%3}, [%4];"
        : "=r"(r[0]), "=r"(r[1]), "=r"(r[2]), "=r"(r[3]) : "r"(addr));
}
__device__ __forceinline__ void cpa16(uint32_t dst, const void* src, bool v) {
    int sz = v ? 16 : 0;
    asm volatile("cp.async.cg.shared.global [%0], [%1], 16, %2;"
                 :: "r"(dst), "l"(src), "r"(sz));
}
__device__ __forceinline__ void cpcommit() { asm volatile("cp.async.commit_group;"); }
__device__ __forceinline__ void cpwait0()  { asm volatile("cp.async.wait_group 0;"); }
__device__ __forceinline__ void cpwait1()  { asm volatile("cp.async.wait_group 1;"); }
__device__ __forceinline__ void cpwait2()  { asm volatile("cp.async.wait_group 2;"); }
__device__ __forceinline__ uint32_t h2u(__half2 h) { return *(uint32_t*)&h; }

// ---------------- weight transpose fp32->half ----------------
__global__ __launch_bounds__(256)
void k_wt(const float* __restrict__ W, __half* __restrict__ dst,
          int Kd, int E, int Kp)
{
    __shared__ float sm[32][33];
    int e0 = blockIdx.x * 32, k0 = blockIdx.y * 32, n = blockIdx.z;
    const float* Wn = W + (size_t)n * Kd * E;
    __half* Tn = dst + (size_t)n * E * Kp;
    int tx = threadIdx.x & 31, ty = threadIdx.x >> 5;
    #pragma unroll
    for (int i = 0; i < 4; i++) {
        int k = k0 + ty + 8 * i, e = e0 + tx;
        sm[ty + 8 * i][tx] = (k < Kd && e < E) ? Wn[(size_t)k * E + e] : 0.f;
    }
    __syncthreads();
    int tx2 = threadIdx.x & 15, ty2 = threadIdx.x >> 4;
    #pragma unroll
    for (int i = 0; i < 2; i++) {
        int e = e0 + ty2 + 16 * i;
        if (e < E) {
            __half2 h = __floats2half2_rn(sm[2*tx2][ty2 + 16*i], sm[2*tx2+1][ty2 + 16*i]);
            *(__half2*)(Tn + (size_t)e * Kp + k0 + 2 * tx2) = h;
        }
    }
}
__global__ __launch_bounds__(256)
void k_wt4(const float* __restrict__ wq, const float* __restrict__ wk,
           const float* __restrict__ wv, const float* __restrict__ wo)
{
    __shared__ float sm[32][33];
    int which = blockIdx.z >> 4, n = blockIdx.z & 15;
    const float* W = (which == 0 ? wq : which == 1 ? wk : which == 2 ? wv : wo)
                     + (size_t)n * D_ * D_;
    __half* Tn = g_wTall + ((size_t)which * N_ + n) * D_ * D_;
    int e0 = blockIdx.x * 32, k0 = blockIdx.y * 32;
    int tx = threadIdx.x & 31, ty = threadIdx.x >> 5;
    #pragma unroll
    for (int i = 0; i < 4; i++)
        sm[ty + 8 * i][tx] = W[(size_t)(k0 + ty + 8 * i) * D_ + e0 + tx];
    __syncthreads();
    int tx2 = threadIdx.x & 15, ty2 = threadIdx.x >> 4;
    #pragma unroll
    for (int i = 0; i < 2; i++) {
        int e = e0 + ty2 + 16 * i;
        __half2 h = __floats2half2_rn(sm[2*tx2][ty2 + 16*i], sm[2*tx2+1][ty2 + 16*i]);
        *(__half2*)(Tn + (size_t)e * D_ + k0 + 2 * tx2) = h;
    }
}

// ---------------- LN (+ optional gate), 2 rows per warp ----------------
template<int WITHGATE>
__global__ __launch_bounds__(256)
void k_ln(const float* __restrict__ X, const float* __restrict__ gamma,
          const float* __restrict__ beta, const float* __restrict__ gw,
          const float* __restrict__ gb)
{
    int w = threadIdx.x >> 5, lane = threadIdx.x & 31;
    int row0 = blockIdx.x * 16 + w * 2;
    int n = (row0 >> 9) & (N_ - 1);
    const float4* xr0 = (const float4*)(X + (size_t)row0 * D_);
    const float4* xr1 = (const float4*)(X + (size_t)(row0 + 1) * D_);
    float4 xa[4], xb[4];
    float a1 = 0.f, a2 = 0.f, a3 = 0.f;
    float b1s = 0.f, b2 = 0.f, b3 = 0.f;
    #pragma unroll
    for (int i = 0; i < 4; i++) { xa[i] = xr0[lane + 32*i]; xb[i] = xr1[lane + 32*i]; }
    #pragma unroll
    for (int i = 0; i < 4; i++) {
        float4 v = xa[i], u = xb[i];
        a1 += v.x + v.y + v.z + v.w;
        a2 += v.x*v.x + v.y*v.y + v.z*v.z + v.w*v.w;
        b1s += u.x + u.y + u.z + u.w;
        b2 += u.x*u.x + u.y*u.y + u.z*u.z + u.w*u.w;
        if (WITHGATE) {
            float4 g4 = ((const float4*)(gw + n*D_))[lane + 32*i];
            a3 += v.x*g4.x + v.y*g4.y + v.z*g4.z + v.w*g4.w;
            b3 += u.x*g4.x + u.y*g4.y + u.z*g4.z + u.w*g4.w;
        }
    }
    #pragma unroll
    for (int off = 16; off; off >>= 1) {
        a1 += __shfl_xor_sync(0xffffffffu, a1, off);
        a2 += __shfl_xor_sync(0xffffffffu, a2, off);
        b1s += __shfl_xor_sync(0xffffffffu, b1s, off);
        b2 += __shfl_xor_sync(0xffffffffu, b2, off);
        if (WITHGATE) {
            a3 += __shfl_xor_sync(0xffffffffu, a3, off);
            b3 += __shfl_xor_sync(0xffffffffu, b3, off);
        }
    }
    float ma = a1 * (1.f/512.f), mb = b1s * (1.f/512.f);
    float ra = rsqrtf(a2 * (1.f/512.f) - ma*ma + 1e-5f);
    float rb = rsqrtf(b2 * (1.f/512.f) - mb*mb + 1e-5f);
    if (WITHGATE && lane == 0) {
        float gbv = gb[n];
        g_gate[row0]     = (a3 + gbv > 0.f) ? 1.f : 0.f;
        g_gate[row0 + 1] = (b3 + gbv > 0.f) ? 1.f : 0.f;
    }
    __half* o0 = g_h + (size_t)row0 * D_;
    __half* o1 = o0 + D_;
    #pragma unroll
    for (int i = 0; i < 4; i++) {
        float4 g4 = ((const float4*)(gamma + n*D_))[lane + 32*i];
        float4 b4 = ((const float4*)(beta  + n*D_))[lane + 32*i];
        float4 v = xa[i], u = xb[i];
        uint2 ua, ub;
        ua.x = h2u(__floats2half2_rn((v.x - ma)*ra*g4.x + b4.x, (v.y - ma)*ra*g4.y + b4.y));
        ua.y = h2u(__floats2half2_rn((v.z - ma)*ra*g4.z + b4.z, (v.w - ma)*ra*g4.w + b4.w));
        ub.x = h2u(__floats2half2_rn((u.x - mb)*rb*g4.x + b4.x, (u.y - mb)*rb*g4.y + b4.y));
        ub.y = h2u(__floats2half2_rn((u.z - mb)*rb*g4.z + b4.z, (u.w - mb)*rb*g4.w + b4.w));
        ((uint2*)o0)[lane + 32*i] = ua;
        ((uint2*)o1)[lane + 32*i] = ub;
    }
}

// ---------------- fp16 GEMM: BK=32, 4-stage cp.async (3 tiles in flight) ----------------
// MODE 0: QKV merged: z=which*16+n; rotary+gate for Q/K, plain for V -> g_qkv
// MODE 2: out = x + acc*gate -> fp32, aux=x ; column-sum partials to g_poolp
// MODE 3: gelu(acc+up_b)     -> half, dst stride FFP, zero pad cols
// MODE 4: out += commit*gate*(acc+down_b)+fsig -> fp32, aux=down_b
template<int K, int NC, int MODE>
__global__ __launch_bounds__(256, 2)
void k_gemm(const __half* __restrict__ act, const __half* __restrict__ wt,
            void* __restrict__ dstv, const float* __restrict__ aux)
{
    __shared__ __half As[4][128 * 40];
    __shared__ __half Bs[4][128 * 40];

    const int z = blockIdx.z;
    const int tid = threadIdx.x;
    const int wid = tid >> 5;
    const int lane = tid & 31;
    const int q = lane & 3, r = lane >> 2;
    const int wm = wid >> 1, wn = wid & 1;
    const int l7 = lane & 7;
    const int ga = (lane >> 3) & 1;
    const int gb = (lane >> 4) & 1;

    int n, which = 0, rbase = 0, t0 = 0, b = 0;
    const __half *Arows, *Brows;
    if (MODE == 0) {
        which = z >> 4;
        n = z & 15;
        b = blockIdx.y >> 2;
        t0 = (blockIdx.y & 3) * 128;
        rbase = (b * N_ + n) * T_ + t0;
        Arows = act + (size_t)rbase * K;
        Brows = wt + (((size_t)which * N_ + n) * NC + blockIdx.x * 128) * K;
    } else {
        n = z;
        b = blockIdx.y >> 2;
        t0 = (blockIdx.y & 3) * 128;
        rbase = (b * N_ + n) * T_ + t0;
        Arows = act + (size_t)rbase * K;
        Brows = wt + ((size_t)n * NC + blockIdx.x * 128) * K;
    }
    const int n0 = blockIdx.x * 128;

    const uint32_t asb = (uint32_t)__cvta_generic_to_shared(&As[0][0]);
    const uint32_t bsb = (uint32_t)__cvta_generic_to_shared(&Bs[0][0]);

    auto stage = [&](int kt, int buf) {
        const int k0 = kt * 32;
        #pragma unroll
        for (int l = 0; l < 2; l++) {
            int idx = tid + 256 * l;
            int m = idx >> 2, c = idx & 3;
            cpa16(asb + (uint32_t)(buf * 5120 + m * 40 + c * 8) * 2,
                  Arows + (size_t)m * K + k0 + c * 8, true);
        }
        #pragma unroll
        for (int l = 0; l < 2; l++) {
            int idx = tid + 256 * l;
            int m = idx >> 2, c = idx & 3;
            bool v = (MODE != 3) || (n0 + m < NC);
            cpa16(bsb + (uint32_t)(buf * 5120 + m * 40 + c * 8) * 2,
                  Brows + (size_t)m * K + k0 + c * 8, v);
        }
    };

    float acc[2][8][4];
    #pragma unroll
    for (int mt = 0; mt < 2; mt++)
        #pragma unroll
        for (int j = 0; j < 8; j++)
            #pragma unroll
            for (int c = 0; c < 4; c++) acc[mt][j][c] = 0.f;

    const uint32_t aoff0 = (uint32_t)((wm*32      + ga*8 + l7) * 40 + gb*8) * 2;
    const uint32_t aoff1 = (uint32_t)((wm*32 + 16 + ga*8 + l7) * 40 + gb*8) * 2;
    uint32_t boffp[4];
    #pragma unroll
    for (int p = 0; p < 4; p++)
        boffp[p] = (uint32_t)((wn*64 + p*16 + gb*8 + l7) * 40 + ga*8) * 2;

    constexpr int NKT = K / 32;
    stage(0, 0); cpcommit();
    stage(1, 1); cpcommit();
    stage(2, 2); cpcommit();
    for (int kt = 0; kt < NKT; kt++) {
        const int cur = kt & 3;
        int rem = NKT - 1 - kt;                 // groups that may stay in flight
        if (rem >= 2)      cpwait2();
        else if (rem == 1) cpwait1();
        else               cpwait0();
        __syncthreads();
        if (kt + 3 < NKT) { stage(kt + 3, (kt + 3) & 3); cpcommit(); }
        const uint32_t ab = asb + (uint32_t)(cur * 5120) * 2;
        const uint32_t bb = bsb + (uint32_t)(cur * 5120) * 2;
        #pragma unroll
        for (int ks2 = 0; ks2 < 2; ks2++) {
            uint32_t a0[4], a1[4];
            ldm4(a0, ab + aoff0 + ks2 * 32);
            ldm4(a1, ab + aoff1 + ks2 * 32);
            #pragma unroll
            for (int p = 0; p < 4; p++) {
                uint32_t bf[4];
                ldm4(bf, bb + boffp[p] + ks2 * 32);
                mma_f16(acc[0][2*p],   a0, bf[0], bf[1]);
                mma_f16(acc[0][2*p+1], a0, bf[2], bf[3]);
                mma_f16(acc[1][2*p],   a1, bf[0], bf[1]);
                mma_f16(acc[1][2*p+1], a1, bf[2], bf[3]);
            }
        }
    }

    // ---------------- epilogues ----------------
    if (MODE == 0) {
        __half* dst = (__half*)dstv + (size_t)which * ROWS * D_;
        int h = blockIdx.x * 2 + wn;
        if (which == 2) {
            #pragma unroll
            for (int mt = 0; mt < 2; mt++) {
                int rloc = wm * 32 + mt * 16 + r;
                __half* d0 = dst + ((size_t)((b*N_+n)*H_ + h)*T_ + t0 + rloc) * DH_ + 2*q;
                __half* d1 = d0 + 8 * DH_;
                #pragma unroll
                for (int j = 0; j < 8; j++) {
                    *(__half2*)(d0 + j*8) = __floats2half2_rn(acc[mt][j][0], acc[mt][j][1]);
                    *(__half2*)(d1 + j*8) = __floats2half2_rn(acc[mt][j][2], acc[mt][j][3]);
                }
            }
        } else {
            float scale = which == 0 ? 0.125f : 1.f;
            float ang = aux[n * H_ + h];
            float ca = cosf(ang) * scale, sa = sinf(ang) * scale;
            #pragma unroll
            for (int mt = 0; mt < 2; mt++) {
                int rloc = wm * 32 + mt * 16 + r;
                int rg = rbase + rloc;
                float g0 = g_gate[rg], g1v = g_gate[rg + 8];
                __half* d0 = dst + ((size_t)((b*N_+n)*H_ + h)*T_ + t0 + rloc) * DH_ + 2*q;
                __half* d1 = d0 + 8 * DH_;
                #pragma unroll
                for (int jj = 0; jj < 4; jj++) {
                    float re0 = acc[mt][jj][0],   re1 = acc[mt][jj][1];
                    float im0 = acc[mt][jj+4][0], im1 = acc[mt][jj+4][1];
                    *(__half2*)(d0 + jj*8)      = __floats2half2_rn((re0*ca - im0*sa)*g0, (re1*ca - im1*sa)*g0);
                    *(__half2*)(d0 + jj*8 + 32) = __floats2half2_rn((re0*sa + im0*ca)*g0, (re1*sa + im1*ca)*g0);
                    float re2 = acc[mt][jj][2],   re3 = acc[mt][jj][3];
                    float im2 = acc[mt][jj+4][2], im3 = acc[mt][jj+4][3];
                    *(__half2*)(d1 + jj*8)      = __floats2half2_rn((re2*ca - im2*sa)*g1v, (re3*ca - im3*sa)*g1v);
                    *(__half2*)(d1 + jj*8 + 32) = __floats2half2_rn((re2*sa + im2*ca)*g1v, (re3*sa + im3*ca)*g1v);
                }
            }
        }
    } else if (MODE == 2) {
        float* dst = (float*)dstv;
        int cb = n0 + wn * 64 + 2*q;
        float ps[8][2];
        #pragma unroll
        for (int j = 0; j < 8; j++) { ps[j][0] = 0.f; ps[j][1] = 0.f; }
        #pragma unroll
        for (int mt = 0; mt < 2; mt++) {
            int rg = rbase + wm * 32 + mt * 16 + r;
            float g0 = g_gate[rg], g1v = g_gate[rg + 8];
            const float* xa = aux + (size_t)rg * D_ + cb;
            float* o = dst + (size_t)rg * D_ + cb;
            #pragma unroll
            for (int j = 0; j < 8; j++) {
                float2 x0 = *(const float2*)(xa + j*8);
                float2 x1 = *(const float2*)(xa + 8*D_ + j*8);
                float2 y0 = make_float2(x0.x + acc[mt][j][0]*g0, x0.y + acc[mt][j][1]*g0);
                float2 y1 = make_float2(x1.x + acc[mt][j][2]*g1v, x1.y + acc[mt][j][3]*g1v);
                *(float2*)(o + j*8) = y0;
                *(float2*)(o + 8*D_ + j*8) = y1;
                ps[j][0] += y0.x + y1.x;
                ps[j][1] += y0.y + y1.y;
            }
        }
        #pragma unroll
        for (int j = 0; j < 8; j++) {
            #pragma unroll
            for (int off = 4; off < 32; off <<= 1) {
                ps[j][0] += __shfl_xor_sync(0xffffffffu, ps[j][0], off);
                ps[j][1] += __shfl_xor_sync(0xffffffffu, ps[j][1], off);
            }
        }
        __syncthreads();
        float* pb = (float*)&As[0][0];
        if (lane < 4) {
            #pragma unroll
            for (int j = 0; j < 8; j++) {
                pb[wm*128 + wn*64 + j*8 + 2*q]     = ps[j][0];
                pb[wm*128 + wn*64 + j*8 + 2*q + 1] = ps[j][1];
            }
        }
        __syncthreads();
        if (tid < 128) {
            float s = pb[tid] + pb[128 + tid] + pb[256 + tid] + pb[384 + tid];
            int ttile = blockIdx.y & 3;
            g_poolp[((size_t)(b*N_+n)*4 + ttile)*512 + n0 + tid] = s;
        }
    } else if (MODE == 3) {
        __half* dst = (__half*)dstv;
        constexpr float ISQ2 = 0.70710678118654752f;
        int cb = n0 + wn * 64 + 2*q;
        #pragma unroll
        for (int mt = 0; mt < 2; mt++) {
            int rg = rbase + wm * 32 + mt * 16 + r;
            #pragma unroll
            for (int j = 0; j < 8; j++) {
                int col = cb + j * 8;
                if (col < FF_) {
                    float b0 = aux[n*FF_ + col], b1 = aux[n*FF_ + col + 1];
                    float z0 = acc[mt][j][0] + b0, z1 = acc[mt][j][1] + b1;
                    float z2 = acc[mt][j][2] + b0, z3 = acc[mt][j][3] + b1;
                    *(__half2*)(dst + (size_t)rg*FFP + col) = __floats2half2_rn(
                        0.5f*z0*(1.f + erff(z0*ISQ2)), 0.5f*z1*(1.f + erff(z1*ISQ2)));
                    *(__half2*)(dst + (size_t)(rg+8)*FFP + col) = __floats2half2_rn(
                        0.5f*z2*(1.f + erff(z2*ISQ2)), 0.5f*z3*(1.f + erff(z3*ISQ2)));
                } else if (col < FFP) {
                    *(__half2*)(dst + (size_t)rg*FFP + col) = __floats2half2_rn(0.f, 0.f);
                    *(__half2*)(dst + (size_t)(rg+8)*FFP + col) = __floats2half2_rn(0.f, 0.f);
                }
            }
        }
    } else { // MODE 4
        float* dst = (float*)dstv;
        float cm = g_commit[b * N_ + n];
        int cb = n0 + wn * 64 + 2*q;
        const float* fs = g_fsig + (size_t)(b*N_+n) * D_ + cb;
        const float* db = aux + n * D_ + cb;
        #pragma unroll
        for (int mt = 0; mt < 2; mt++) {
            int rg = rbase + wm * 32 + mt * 16 + r;
            float cg0 = cm * g_gate[rg], cg1 = cm * g_gate[rg + 8];
            float* o = dst + (size_t)rg * D_ + cb;
            #pragma unroll
            for (int j = 0; j < 8; j++) {
                float2 bb = *(const float2*)(db + j*8);
                float2 ff = *(const float2*)(fs + j*8);
                float2 x0 = *(float2*)(o + j*8);
                float2 x1 = *(float2*)(o + 8*D_ + j*8);
                x0.x += cg0*(acc[mt][j][0] + bb.x) + ff.x;
                x0.y += cg0*(acc[mt][j][1] + bb.y) + ff.y;
                x1.x += cg1*(acc[mt][j][2] + bb.x) + ff.x;
                x1.y += cg1*(acc[mt][j][3] + bb.y) + ff.y;
                *(float2*)(o + j*8) = x0;
                *(float2*)(o + 8*D_ + j*8) = x1;
            }
        }
    }
}

// ---------------- flash attention: 4-buffer KV ring, P in registers ----------------
constexpr int AQ = 0;
constexpr int AK = 128 * 72;
constexpr int AV = AK + 4 * 64 * 72;
constexpr int ATTN_SMEM_HALVES = AV + 4 * 64 * 72;

__global__ __launch_bounds__(256)
void k_attn()
{
    extern __shared__ __half sh[];

    const int bid = blockIdx.x;
    const int qt  = bid & 3;
    const int bnh = bid >> 2;
    const int bn = bnh >> 3, h = bnh & 7;
    const __half* Qb = g_qkv + (size_t)bnh * T_ * DH_ + (size_t)qt * 128 * DH_;
    const __half* Kb = g_qkv + (size_t)ROWS * D_ + (size_t)bnh * T_ * DH_;
    const __half* Vb = g_qkv + (size_t)2 * ROWS * D_ + (size_t)bnh * T_ * DH_;

    const int tid  = threadIdx.x;
    const int wid  = tid >> 5;
    const int lane = tid & 31;
    const int q = lane & 3, r = lane >> 2;
    const int rm = wid * 16;
    const int l7 = lane & 7;
    const int ga = (lane >> 3) & 1;
    const int gb = (lane >> 4) & 1;

    const uint32_t shb = (uint32_t)__cvta_generic_to_shared(sh);
    const uint32_t qsb = shb + AQ * 2;
    const uint32_t ksb = shb + AK * 2;
    const uint32_t vsb = shb + AV * 2;

    const uint32_t aoff = (uint32_t)((rm + ga*8 + l7) * 72 + gb*8) * 2;
    uint32_t boffp[4], boffv[4];
    #pragma unroll
    for (int p = 0; p < 4; p++) {
        boffp[p] = (uint32_t)((p*16 + gb*8 + l7) * 72 + ga*8) * 2;
        boffv[p] = (uint32_t)((ga*8 + l7) * 72 + p*16 + gb*8) * 2;
    }

    #pragma unroll
    for (int l = 0; l < 4; l++) {
        int idx = tid + 256 * l;
        int row = idx >> 3, c = idx & 7;
        cpa16(qsb + (uint32_t)(row * 72 + c * 8) * 2, Qb + (size_t)row * 64 + c * 8, true);
    }
    auto stageKV = [&](int it, int buf) {
        int s0 = it * 64;
        uint32_t kb = ksb + (uint32_t)(buf * 64 * 72) * 2;
        uint32_t vb = vsb + (uint32_t)(buf * 64 * 72) * 2;
        #pragma unroll
        for (int l = 0; l < 2; l++) {
            int idx = tid + 256 * l;
            int row = idx >> 3, c = idx & 7;
            cpa16(kb + (uint32_t)(row * 72 + c * 8) * 2,
                  Kb + (size_t)(s0 + row) * 64 + c * 8, true);
            cpa16(vb + (uint32_t)(row * 72 + c * 8) * 2,
                  Vb + (size_t)(s0 + row) * 64 + c * 8, true);
        }
    };

    float o[8][4];
    #pragma unroll
    for (int j = 0; j < 8; j++)
        #pragma unroll
        for (int c = 0; c < 4; c++) o[j][c] = 0.f;
    float l0 = 0.f, l1 = 0.f;
    uint32_t qf[4][4];

    stageKV(0, 0); cpcommit();
    stageKV(1, 1); cpcommit();
    stageKV(2, 2); cpcommit();
    for (int it = 0; it < 8; it++) {
        const int cur = it & 3;
        int rem = 7 - it;
        if (rem >= 2)      cpwait2();
        else if (rem == 1) cpwait1();
        else               cpwait0();
        __syncthreads();
        if (it + 3 < 8) { stageKV(it + 3, (it + 3) & 3); cpcommit(); }
        const uint32_t kb = ksb + (uint32_t)(cur * 64 * 72) * 2;
        const uint32_t vb = vsb + (uint32_t)(cur * 64 * 72) * 2;

        if (it == 0) {
            #pragma unroll
            for (int c = 0; c < 4; c++) ldm4(qf[c], qsb + aoff + c * 32);
        }

        float s[8][4];
        #pragma unroll
        for (int j = 0; j < 8; j++)
            #pragma unroll
            for (int c = 0; c < 4; c++) s[j][c] = 0.f;
        #pragma unroll
        for (int c = 0; c < 4; c++) {
            #pragma unroll
            for (int p = 0; p < 4; p++) {
                uint32_t bf[4];
                ldm4(bf, kb + boffp[p] + c * 32);
                mma_f16(s[2*p],   qf[c], bf[0], bf[1]);
                mma_f16(s[2*p+1], qf[c], bf[2], bf[3]);
            }
        }

        #pragma unroll
        for (int c = 0; c < 4; c++) {
            float e00 = __expf(s[2*c][0]),   e01 = __expf(s[2*c][1]);
            float e02 = __expf(s[2*c][2]),   e03 = __expf(s[2*c][3]);
            float e10 = __expf(s[2*c+1][0]), e11 = __expf(s[2*c+1][1]);
            float e12 = __expf(s[2*c+1][2]), e13 = __expf(s[2*c+1][3]);
            l0 += e00 + e01 + e10 + e11;
            l1 += e02 + e03 + e12 + e13;
            uint32_t a[4];
            a[0] = h2u(__floats2half2_rn(e00, e01));
            a[1] = h2u(__floats2half2_rn(e02, e03));
            a[2] = h2u(__floats2half2_rn(e10, e11));
            a[3] = h2u(__floats2half2_rn(e12, e13));
            #pragma unroll
            for (int p = 0; p < 4; p++) {
                uint32_t bf[4];
                ldm4t(bf, vb + boffv[p] + (uint32_t)(c * 16 * 72) * 2);
                mma_f16(o[2*p],   a, bf[0], bf[1]);
                mma_f16(o[2*p+1], a, bf[2], bf[3]);
            }
        }
    }

    l0 += __shfl_xor_sync(0xffffffffu, l0, 1);
    l0 += __shfl_xor_sync(0xffffffffu, l0, 2);
    l1 += __shfl_xor_sync(0xffffffffu, l1, 1);
    l1 += __shfl_xor_sync(0xffffffffu, l1, 2);
    float i0 = 1.f / l0, i1 = 1.f / l1;
    __half* d0 = g_attn + ((size_t)bn * T_ + qt * 128 + rm + r) * D_ + h * DH_ + 2 * q;
    __half* d1 = d0 + (size_t)8 * D_;
    #pragma unroll
    for (int j = 0; j < 8; j++) {
        *(__half2*)(d0 + j * 8) = __floats2half2_rn(o[j][0] * i0, o[j][1] * i0);
        *(__half2*)(d1 + j * 8) = __floats2half2_rn(o[j][2] * i1, o[j][3] * i1);
    }
}

// ---------------- commit + center + h_res + (cos,sin) ----------------
__global__ __launch_bounds__(128)
void k_small_a(const float* __restrict__ cw, const float* __restrict__ cb,
               const float* __restrict__ centw, const float* __restrict__ centb,
               const float* __restrict__ fiw)
{
    int bn = blockIdx.x, n = bn & (N_ - 1), tid = threadIdx.x;
    __shared__ float sp[D_];
    __shared__ float sc[D_];
    __shared__ float red[4];

    float4 p4 = make_float4(0.f, 0.f, 0.f, 0.f);
    #pragma unroll
    for (int c = 0; c < 4; c++) {
        float4 v = ((const float4*)g_poolp)[(bn * 4 + c) * 128 + tid];
        p4.x += v.x; p4.y += v.y; p4.z += v.z; p4.w += v.w;
    }
    p4.x *= (1.f/512.f); p4.y *= (1.f/512.f); p4.z *= (1.f/512.f); p4.w *= (1.f/512.f);
    ((float4*)sp)[tid] = p4;
    float4 w4 = ((const float4*)(cw + n * D_))[tid];
    float loc = p4.x*w4.x + p4.y*w4.y + p4.z*w4.z + p4.w*w4.w;
    #pragma unroll
    for (int off = 16; off; off >>= 1) loc += __shfl_down_sync(0xffffffffu, loc, off);
    if ((tid & 31) == 0) red[tid >> 5] = loc;
    __syncthreads();
    if (tid == 0) {
        float tot = red[0] + red[1] + red[2] + red[3] + cb[n];
        g_commit[bn] = 1.f / (1.f + expf(-tot));
    }

    float4 acc = make_float4(0.f, 0.f, 0.f, 0.f);
    const float4* cwp = (const float4*)(centw + (size_t)n * D_ * D_);
    for (int d = 0; d < D_; d++) {
        float pd = sp[d];
        float4 w = cwp[d * 128 + tid];
        acc.x = fmaf(pd, w.x, acc.x);
        acc.y = fmaf(pd, w.y, acc.y);
        acc.z = fmaf(pd, w.z, acc.z);
        acc.w = fmaf(pd, w.w, acc.w);
    }
    float4 cbv = ((const float4*)(centb + n * D_))[tid];
    acc.x = tanhf(acc.x + cbv.x);
    acc.y = tanhf(acc.y + cbv.y);
    acc.z = tanhf(acc.z + cbv.z);
    acc.w = tanhf(acc.w + cbv.w);
    ((float4*)sc)[tid] = acc;
    __syncthreads();

    float4 hr = make_float4(0.f, 0.f, 0.f, 0.f);
    const float4* fip = (const float4*)fiw;
    for (int d = 0; d < D_; d++) {
        float cd = sc[d];
        float4 w = fip[d * 128 + tid];
        hr.x = fmaf(cd, w.x, hr.x);
        hr.y = fmaf(cd, w.y, hr.y);
        hr.z = fmaf(cd, w.z, hr.z);
        hr.w = fmaf(cd, w.w, hr.w);
    }
    ((float4*)g_hres)[bn * 128 + tid] = hr;

    float rex = hr.x + 1e-8f, imx = hr.y + 1e-8f;
    float rr = fmaxf(sqrtf(rex*rex + imx*imx), 1e-30f);
    g_cs_c[bn * 256 + tid * 2]     = rex / rr;
    g_cs_s[bn * 256 + tid * 2]     = imx / rr;
    float rez = hr.z + 1e-8f, imw = hr.w + 1e-8f;
    rr = fmaxf(sqrtf(rez*rez + imw*imw), 1e-30f);
    g_cs_c[bn * 256 + tid * 2 + 1] = rez / rr;
    g_cs_s[bn * 256 + tid * 2 + 1] = imw / rr;
}

// ---------------- resonance gram matrix ----------------
__global__ __launch_bounds__(256)
void k_racc()
{
    __shared__ float cc[N_][257];
    __shared__ float sn[N_][257];
    int b = blockIdx.x, tid = threadIdx.x;
    #pragma unroll
    for (int i = 0; i < 16; i++) {
        int idx = tid + 256 * i;
        int nn = idx >> 8, p = idx & 255;
        cc[nn][p] = g_cs_c[b * 4096 + idx];
        sn[nn][p] = g_cs_s[b * 4096 + idx];
    }
    __syncthreads();
    int mrow = tid >> 4, ncol = tid & 15;
    float acc = 0.f;
    for (int p = 0; p < 256; p++)
        acc += cc[mrow][p] * cc[ncol][p] + sn[mrow][p] * sn[ncol][p];
    g_racc[b * 256 + tid] = acc * (1.f / 256.f);
}

// ---------------- recv + field_signal ----------------
__global__ __launch_bounds__(128)
void k_fieldsig(const float* __restrict__ fow, const float* __restrict__ condp)
{
    int b = blockIdx.x >> 4, mm = blockIdx.x & 15, tid = threadIdx.x;
    __shared__ float rv[D_];
    __shared__ float wgt[N_];
    if (tid < 16) wgt[tid] = g_racc[b * 256 + mm * 16 + tid] * g_commit[b * 16 + tid];
    __syncthreads();
    float4 acc = make_float4(0.f, 0.f, 0.f, 0.f);
    const float4* hp = (const float4*)g_hres;
    #pragma unroll
    for (int n2 = 0; n2 < 16; n2++) {
        float w = wgt[n2];
        float4 h4 = hp[(b * 16 + n2) * 128 + tid];
        acc.x = fmaf(w, h4.x, acc.x);
        acc.y = fmaf(w, h4.y, acc.y);
        acc.z = fmaf(w, h4.z, acc.z);
        acc.w = fmaf(w, h4.w, acc.w);
    }
    float cond = condp[0];
    acc.x *= cond; acc.y *= cond; acc.z *= cond; acc.w *= cond;
    ((float4*)rv)[tid] = acc;
    __syncthreads();
    float4 fs = make_float4(0.f, 0.f, 0.f, 0.f);
    const float4* fp = (const float4*)fow;
    for (int d = 0; d < D_; d++) {
        float rd = rv[d];
        float4 w = fp[d * 128 + tid];
        fs.x = fmaf(rd, w.x, fs.x);
        fs.y = fmaf(rd, w.y, fs.y);
        fs.z = fmaf(rd, w.z, fs.z);
        fs.w = fmaf(rd, w.w, fs.w);
    }
    ((float4*)g_fsig)[blockIdx.x * 128 + tid] = fs;
}

// ---------------- launch ----------------
extern "C" void kernel_launch(void* const* d_in, const int* in_sizes, int n_in,
                              void* d_out, int out_size)
{
    const float* x        = (const float*)d_in[0];
    const float* gate_w   = (const float*)d_in[1];
    const float* gate_b   = (const float*)d_in[2];
    const float* ln1_g    = (const float*)d_in[3];
    const float* ln1_b    = (const float*)d_in[4];
    const float* wq       = (const float*)d_in[5];
    const float* wk       = (const float*)d_in[6];
    const float* wv       = (const float*)d_in[7];
    const float* wo       = (const float*)d_in[8];
    const float* phase    = (const float*)d_in[9];
    const float* ln2_g    = (const float*)d_in[10];
    const float* ln2_b    = (const float*)d_in[11];
    const float* up_w     = (const float*)d_in[12];
    const float* up_b     = (const float*)d_in[13];
    const float* down_w   = (const float*)d_in[14];
    const float* down_b   = (const float*)d_in[15];
    const float* commit_w = (const float*)d_in[16];
    const float* commit_b = (const float*)d_in[17];
    const float* center_w = (const float*)d_in[18];
    const float* center_b = (const float*)d_in[19];
    const float* fiw      = (const float*)d_in[20];
    const float* fow      = (const float*)d_in[21];
    const float* cond     = (const float*)d_in[22];
    float* out = (float*)d_out;

    __half *p_h, *p_qkv, *p_attn, *p_up, *p_wTall, *p_upT, *p_dnT;
    cudaGetSymbolAddress((void**)&p_h,     g_h);
    cudaGetSymbolAddress((void**)&p_qkv,   g_qkv);
    cudaGetSymbolAddress((void**)&p_attn,  g_attn);
    cudaGetSymbolAddress((void**)&p_up,    g_up);
    cudaGetSymbolAddress((void**)&p_wTall, g_wTall);
    cudaGetSymbolAddress((void**)&p_upT,   g_upT);
    cudaGetSymbolAddress((void**)&p_dnT,   g_dnT);
    const size_t WSZ = (size_t)N_ * D_ * D_;

    cudaFuncSetAttribute(k_attn, cudaFuncAttributeMaxDynamicSharedMemorySize,
                         ATTN_SMEM_HALVES * 2);

    // 0. weight prep
    k_wt4<<<dim3(16, 16, 64), 256>>>(wq, wk, wv, wo);
    k_wt<<<dim3(26, 16, 16), 256>>>(up_w,   p_upT, 512, 828, 512);
    k_wt<<<dim3(16, 26, 16), 256>>>(down_w, p_dnT, 828, 512, 832);

    // 1. gate + LN1
    k_ln<1><<<ROWS / 16, 256>>>(x, ln1_g, ln1_b, gate_w, gate_b);

    // 2. Q+K+V merged projection
    k_gemm<512, 512, 0><<<dim3(4, 8, 48), 256>>>(p_h, p_wTall, p_qkv, phase);

    // 3. attention
    k_attn<<<1024, 256, ATTN_SMEM_HALVES * 2>>>();

    // 4. x1 = x + (attn@wo)*gate -> out  (+ fused pooling partials)
    k_gemm<512, 512, 2><<<dim3(4, 8, 16), 256>>>(p_attn, p_wTall + 3*WSZ, out, x);

    // 5. small chain
    k_small_a<<<32, 128>>>(commit_w, commit_b, center_w, center_b, fiw);
    k_racc<<<2, 256>>>();
    k_fieldsig<<<32, 128>>>(fow, cond);

    // 6. FFN + final fold
    k_ln<0><<<ROWS / 16, 256>>>(out, ln2_g, ln2_b, nullptr, nullptr);
    k_gemm<512, 828, 3><<<dim3(7, 8, 16), 256>>>(p_h, p_upT, p_up, up_b);
    k_gemm<832, 512, 4><<<dim3(4, 8, 16), 256>>>(p_up, p_dnT, out, down_b);
}

// round 17
// speedup vs baseline: 1.0427x; 1.0427x over previous
#include <cuda_runtime.h>
#include <cuda_fp16.h>
#include <math.h>
#include <stdint.h>

// ---------------- problem constants ----------------
constexpr int B_  = 2;
constexpr int N_  = 16;
constexpr int T_  = 512;
constexpr int D_  = 512;
constexpr int H_  = 8;
constexpr int DH_ = 64;
constexpr int FF_ = 828;
constexpr int FFP = 832;            // padded
constexpr int ROWS = B_ * N_ * T_;  // 16384

// ---------------- scratch ----------------
__device__ __align__(16) __half g_h   [(size_t)ROWS * D_];
__device__ float  g_gate[ROWS];
__device__ __align__(16) __half g_qkv [(size_t)3 * ROWS * D_];  // [which][b,n,h,t,dh]
__device__ __align__(16) __half g_attn[(size_t)ROWS * D_];      // [bn][t][512]
__device__ __align__(16) __half g_up  [(size_t)ROWS * FFP];     // zero-padded 828..831
__device__ float  g_poolp[B_ * N_ * 4 * D_];                    // [bn][ttile][512]
__device__ float  g_commit[B_ * N_];
__device__ float  g_hres[B_ * N_ * D_];
__device__ float  g_cs_c[B_ * N_ * 256];
__device__ float  g_cs_s[B_ * N_ * 256];
__device__ float  g_racc[B_ * N_ * N_];
__device__ float  g_fsig[B_ * N_ * D_];
// transposed half weights
__device__ __align__(16) __half g_wTall[(size_t)4 * N_ * D_ * D_];   // q,k,v,o : [n][out][k]
__device__ __align__(16) __half g_upT [(size_t)N_ * FF_ * D_];       // [n][828][512]
__device__ __align__(16) __half g_dnT [(size_t)N_ * D_ * FFP];       // [n][512][832]

// ---------------- helpers ----------------
__device__ __forceinline__ void mma_f16(float c[4], const uint32_t a[4],
                                        uint32_t b0, uint32_t b1)
{
    asm volatile(
        "mma.sync.aligned.m16n8k16.row.col.f32.f16.f16.f32 "
        "{%0,%1,%2,%3}, {%4,%5,%6,%7}, {%8,%9}, {%0,%1,%2,%3};"
        : "+f"(c[0]), "+f"(c[1]), "+f"(c[2]), "+f"(c[3])
        : "r"(a[0]), "r"(a[1]), "r"(a[2]), "r"(a[3]), "r"(b0), "r"(b1));
}
__device__ __forceinline__ void ldm4(uint32_t r[4], uint32_t addr) {
    asm volatile("ldmatrix.sync.aligned.m8n8.x4.shared.b16 {%0,%1,%2,%3}, [%4];"
        : "=r"(r[0]), "=r"(r[1]), "=r"(r[2]), "=r"(r[3]) : "r"(addr));
}
__device__ __forceinline__ void ldm4t(uint32_t r[4], uint32_t addr) {
    asm volatile("ldmatrix.sync.aligned.m8n8.x4.trans.shared.b16 {%0,%1,%2,%3}, [%4];"
        : "=r"(r[0]), "=r"(r[1]), "=r"(r[2]), "=r"(r[3]) : "r"(addr));
}
__device__ __forceinline__ void cpa16(uint32_t dst, const void* src, bool v) {
    int sz = v ? 16 : 0;
    asm volatile("cp.async.cg.shared.global [%0], [%1], 16, %2;"
                 :: "r"(dst), "l"(src), "r"(sz));
}
__device__ __forceinline__ void cpcommit() { asm volatile("cp.async.commit_group;"); }
__device__ __forceinline__ void cpwait0()  { asm volatile("cp.async.wait_group 0;"); }
__device__ __forceinline__ void cpwait1()  { asm volatile("cp.async.wait_group 1;"); }
__device__ __forceinline__ uint32_t h2u(__half2 h) { return *(uint32_t*)&h; }

// ---------------- weight transpose fp32->half ----------------
__global__ __launch_bounds__(256)
void k_wt(const float* __restrict__ W, __half* __restrict__ dst,
          int Kd, int E, int Kp)
{
    __shared__ float sm[32][33];
    int e0 = blockIdx.x * 32, k0 = blockIdx.y * 32, n = blockIdx.z;
    const float* Wn = W + (size_t)n * Kd * E;
    __half* Tn = dst + (size_t)n * E * Kp;
    int tx = threadIdx.x & 31, ty = threadIdx.x >> 5;
    #pragma unroll
    for (int i = 0; i < 4; i++) {
        int k = k0 + ty + 8 * i, e = e0 + tx;
        sm[ty + 8 * i][tx] = (k < Kd && e < E) ? Wn[(size_t)k * E + e] : 0.f;
    }
    __syncthreads();
    int tx2 = threadIdx.x & 15, ty2 = threadIdx.x >> 4;
    #pragma unroll
    for (int i = 0; i < 2; i++) {
        int e = e0 + ty2 + 16 * i;
        if (e < E) {
            __half2 h = __floats2half2_rn(sm[2*tx2][ty2 + 16*i], sm[2*tx2+1][ty2 + 16*i]);
            *(__half2*)(Tn + (size_t)e * Kp + k0 + 2 * tx2) = h;
        }
    }
}
__global__ __launch_bounds__(256)
void k_wt4(const float* __restrict__ wq, const float* __restrict__ wk,
           const float* __restrict__ wv, const float* __restrict__ wo)
{
    __shared__ float sm[32][33];
    int which = blockIdx.z >> 4, n = blockIdx.z & 15;
    const float* W = (which == 0 ? wq : which == 1 ? wk : which == 2 ? wv : wo)
                     + (size_t)n * D_ * D_;
    __half* Tn = g_wTall + ((size_t)which * N_ + n) * D_ * D_;
    int e0 = blockIdx.x * 32, k0 = blockIdx.y * 32;
    int tx = threadIdx.x & 31, ty = threadIdx.x >> 5;
    #pragma unroll
    for (int i = 0; i < 4; i++)
        sm[ty + 8 * i][tx] = W[(size_t)(k0 + ty + 8 * i) * D_ + e0 + tx];
    __syncthreads();
    int tx2 = threadIdx.x & 15, ty2 = threadIdx.x >> 4;
    #pragma unroll
    for (int i = 0; i < 2; i++) {
        int e = e0 + ty2 + 16 * i;
        __half2 h = __floats2half2_rn(sm[2*tx2][ty2 + 16*i], sm[2*tx2+1][ty2 + 16*i]);
        *(__half2*)(Tn + (size_t)e * D_ + k0 + 2 * tx2) = h;
    }
}

// ---------------- LN (+ optional gate), 2 rows per warp ----------------
template<int WITHGATE>
__global__ __launch_bounds__(256)
void k_ln(const float* __restrict__ X, const float* __restrict__ gamma,
          const float* __restrict__ beta, const float* __restrict__ gw,
          const float* __restrict__ gb)
{
    int w = threadIdx.x >> 5, lane = threadIdx.x & 31;
    int row0 = blockIdx.x * 16 + w * 2;
    int n = (row0 >> 9) & (N_ - 1);
    const float4* xr0 = (const float4*)(X + (size_t)row0 * D_);
    const float4* xr1 = (const float4*)(X + (size_t)(row0 + 1) * D_);
    float4 xa[4], xb[4];
    float a1 = 0.f, a2 = 0.f, a3 = 0.f;
    float b1s = 0.f, b2 = 0.f, b3 = 0.f;
    #pragma unroll
    for (int i = 0; i < 4; i++) { xa[i] = xr0[lane + 32*i]; xb[i] = xr1[lane + 32*i]; }
    #pragma unroll
    for (int i = 0; i < 4; i++) {
        float4 v = xa[i], u = xb[i];
        a1 += v.x + v.y + v.z + v.w;
        a2 += v.x*v.x + v.y*v.y + v.z*v.z + v.w*v.w;
        b1s += u.x + u.y + u.z + u.w;
        b2 += u.x*u.x + u.y*u.y + u.z*u.z + u.w*u.w;
        if (WITHGATE) {
            float4 g4 = ((const float4*)(gw + n*D_))[lane + 32*i];
            a3 += v.x*g4.x + v.y*g4.y + v.z*g4.z + v.w*g4.w;
            b3 += u.x*g4.x + u.y*g4.y + u.z*g4.z + u.w*g4.w;
        }
    }
    #pragma unroll
    for (int off = 16; off; off >>= 1) {
        a1 += __shfl_xor_sync(0xffffffffu, a1, off);
        a2 += __shfl_xor_sync(0xffffffffu, a2, off);
        b1s += __shfl_xor_sync(0xffffffffu, b1s, off);
        b2 += __shfl_xor_sync(0xffffffffu, b2, off);
        if (WITHGATE) {
            a3 += __shfl_xor_sync(0xffffffffu, a3, off);
            b3 += __shfl_xor_sync(0xffffffffu, b3, off);
        }
    }
    float ma = a1 * (1.f/512.f), mb = b1s * (1.f/512.f);
    float ra = rsqrtf(a2 * (1.f/512.f) - ma*ma + 1e-5f);
    float rb = rsqrtf(b2 * (1.f/512.f) - mb*mb + 1e-5f);
    if (WITHGATE && lane == 0) {
        float gbv = gb[n];
        g_gate[row0]     = (a3 + gbv > 0.f) ? 1.f : 0.f;
        g_gate[row0 + 1] = (b3 + gbv > 0.f) ? 1.f : 0.f;
    }
    __half* o0 = g_h + (size_t)row0 * D_;
    __half* o1 = o0 + D_;
    #pragma unroll
    for (int i = 0; i < 4; i++) {
        float4 g4 = ((const float4*)(gamma + n*D_))[lane + 32*i];
        float4 b4 = ((const float4*)(beta  + n*D_))[lane + 32*i];
        float4 v = xa[i], u = xb[i];
        uint2 ua, ub;
        ua.x = h2u(__floats2half2_rn((v.x - ma)*ra*g4.x + b4.x, (v.y - ma)*ra*g4.y + b4.y));
        ua.y = h2u(__floats2half2_rn((v.z - ma)*ra*g4.z + b4.z, (v.w - ma)*ra*g4.w + b4.w));
        ub.x = h2u(__floats2half2_rn((u.x - mb)*rb*g4.x + b4.x, (u.y - mb)*rb*g4.y + b4.y));
        ub.y = h2u(__floats2half2_rn((u.z - mb)*rb*g4.z + b4.z, (u.w - mb)*rb*g4.w + b4.w));
        ((uint2*)o0)[lane + 32*i] = ua;
        ((uint2*)o1)[lane + 32*i] = ub;
    }
}

// ---------------- fp16 GEMM: 3-stage cp.async, 1 sync/tile (proven R15) ----------------
// MODE 0: QKV merged: z=which*16+n; rotary+gate for Q/K, plain for V -> g_qkv
// MODE 2: out = x + acc*gate -> fp32, aux=x ; column-sum partials to g_poolp
// MODE 3: gelu(acc+up_b)     -> half, dst stride FFP, zero pad cols
// MODE 4: out += commit*gate*(acc+down_b)+fsig -> fp32, aux=down_b
template<int K, int NC, int MODE>
__global__ __launch_bounds__(256, 2)
void k_gemm(const __half* __restrict__ act, const __half* __restrict__ wt,
            void* __restrict__ dstv, const float* __restrict__ aux)
{
    __shared__ __half As[3][128 * 40];
    __shared__ __half Bs[3][128 * 40];

    const int z = blockIdx.z;
    const int tid = threadIdx.x;
    const int wid = tid >> 5;
    const int lane = tid & 31;
    const int q = lane & 3, r = lane >> 2;
    const int wm = wid >> 1, wn = wid & 1;
    const int l7 = lane & 7;
    const int ga = (lane >> 3) & 1;
    const int gb = (lane >> 4) & 1;

    int n, which = 0, rbase = 0, t0 = 0, b = 0;
    const __half *Arows, *Brows;
    if (MODE == 0) {
        which = z >> 4;
        n = z & 15;
        b = blockIdx.y >> 2;
        t0 = (blockIdx.y & 3) * 128;
        rbase = (b * N_ + n) * T_ + t0;
        Arows = act + (size_t)rbase * K;
        Brows = wt + (((size_t)which * N_ + n) * NC + blockIdx.x * 128) * K;
    } else {
        n = z;
        b = blockIdx.y >> 2;
        t0 = (blockIdx.y & 3) * 128;
        rbase = (b * N_ + n) * T_ + t0;
        Arows = act + (size_t)rbase * K;
        Brows = wt + ((size_t)n * NC + blockIdx.x * 128) * K;
    }
    const int n0 = blockIdx.x * 128;

    const uint32_t asb = (uint32_t)__cvta_generic_to_shared(&As[0][0]);
    const uint32_t bsb = (uint32_t)__cvta_generic_to_shared(&Bs[0][0]);

    auto stage = [&](int kt, int buf) {
        const int k0 = kt * 32;
        #pragma unroll
        for (int l = 0; l < 2; l++) {
            int idx = tid + 256 * l;
            int m = idx >> 2, c = idx & 3;
            cpa16(asb + (uint32_t)(buf * 5120 + m * 40 + c * 8) * 2,
                  Arows + (size_t)m * K + k0 + c * 8, true);
        }
        #pragma unroll
        for (int l = 0; l < 2; l++) {
            int idx = tid + 256 * l;
            int m = idx >> 2, c = idx & 3;
            bool v = (MODE != 3) || (n0 + m < NC);
            cpa16(bsb + (uint32_t)(buf * 5120 + m * 40 + c * 8) * 2,
                  Brows + (size_t)m * K + k0 + c * 8, v);
        }
    };

    float acc[2][8][4];
    #pragma unroll
    for (int mt = 0; mt < 2; mt++)
        #pragma unroll
        for (int j = 0; j < 8; j++)
            #pragma unroll
            for (int c = 0; c < 4; c++) acc[mt][j][c] = 0.f;

    const uint32_t aoff0 = (uint32_t)((wm*32      + ga*8 + l7) * 40 + gb*8) * 2;
    const uint32_t aoff1 = (uint32_t)((wm*32 + 16 + ga*8 + l7) * 40 + gb*8) * 2;
    uint32_t boffp[4];
    #pragma unroll
    for (int p = 0; p < 4; p++)
        boffp[p] = (uint32_t)((wn*64 + p*16 + gb*8 + l7) * 40 + ga*8) * 2;

    constexpr int NKT = K / 32;
    stage(0, 0); cpcommit();
    stage(1, 1); cpcommit();
    for (int kt = 0; kt < NKT; kt++) {
        const int cur = kt % 3;
        if (kt == NKT - 1) cpwait0(); else cpwait1();
        __syncthreads();
        if (kt + 2 < NKT) { stage(kt + 2, (kt + 2) % 3); cpcommit(); }
        const uint32_t ab = asb + (uint32_t)(cur * 5120) * 2;
        const uint32_t bb = bsb + (uint32_t)(cur * 5120) * 2;
        #pragma unroll
        for (int ks2 = 0; ks2 < 2; ks2++) {
            uint32_t a0[4], a1[4];
            ldm4(a0, ab + aoff0 + ks2 * 32);
            ldm4(a1, ab + aoff1 + ks2 * 32);
            #pragma unroll
            for (int p = 0; p < 4; p++) {
                uint32_t bf[4];
                ldm4(bf, bb + boffp[p] + ks2 * 32);
                mma_f16(acc[0][2*p],   a0, bf[0], bf[1]);
                mma_f16(acc[0][2*p+1], a0, bf[2], bf[3]);
                mma_f16(acc[1][2*p],   a1, bf[0], bf[1]);
                mma_f16(acc[1][2*p+1], a1, bf[2], bf[3]);
            }
        }
    }

    // ---------------- epilogues ----------------
    if (MODE == 0) {
        __half* dst = (__half*)dstv + (size_t)which * ROWS * D_;
        int h = blockIdx.x * 2 + wn;
        if (which == 2) {
            #pragma unroll
            for (int mt = 0; mt < 2; mt++) {
                int rloc = wm * 32 + mt * 16 + r;
                __half* d0 = dst + ((size_t)((b*N_+n)*H_ + h)*T_ + t0 + rloc) * DH_ + 2*q;
                __half* d1 = d0 + 8 * DH_;
                #pragma unroll
                for (int j = 0; j < 8; j++) {
                    *(__half2*)(d0 + j*8) = __floats2half2_rn(acc[mt][j][0], acc[mt][j][1]);
                    *(__half2*)(d1 + j*8) = __floats2half2_rn(acc[mt][j][2], acc[mt][j][3]);
                }
            }
        } else {
            float scale = which == 0 ? 0.125f : 1.f;
            float ang = aux[n * H_ + h];
            float ca = cosf(ang) * scale, sa = sinf(ang) * scale;
            #pragma unroll
            for (int mt = 0; mt < 2; mt++) {
                int rloc = wm * 32 + mt * 16 + r;
                int rg = rbase + rloc;
                float g0 = g_gate[rg], g1v = g_gate[rg + 8];
                __half* d0 = dst + ((size_t)((b*N_+n)*H_ + h)*T_ + t0 + rloc) * DH_ + 2*q;
                __half* d1 = d0 + 8 * DH_;
                #pragma unroll
                for (int jj = 0; jj < 4; jj++) {
                    float re0 = acc[mt][jj][0],   re1 = acc[mt][jj][1];
                    float im0 = acc[mt][jj+4][0], im1 = acc[mt][jj+4][1];
                    *(__half2*)(d0 + jj*8)      = __floats2half2_rn((re0*ca - im0*sa)*g0, (re1*ca - im1*sa)*g0);
                    *(__half2*)(d0 + jj*8 + 32) = __floats2half2_rn((re0*sa + im0*ca)*g0, (re1*sa + im1*ca)*g0);
                    float re2 = acc[mt][jj][2],   re3 = acc[mt][jj][3];
                    float im2 = acc[mt][jj+4][2], im3 = acc[mt][jj+4][3];
                    *(__half2*)(d1 + jj*8)      = __floats2half2_rn((re2*ca - im2*sa)*g1v, (re3*ca - im3*sa)*g1v);
                    *(__half2*)(d1 + jj*8 + 32) = __floats2half2_rn((re2*sa + im2*ca)*g1v, (re3*sa + im3*ca)*g1v);
                }
            }
        }
    } else if (MODE == 2) {
        float* dst = (float*)dstv;
        int cb = n0 + wn * 64 + 2*q;
        float ps[8][2];
        #pragma unroll
        for (int j = 0; j < 8; j++) { ps[j][0] = 0.f; ps[j][1] = 0.f; }
        #pragma unroll
        for (int mt = 0; mt < 2; mt++) {
            int rg = rbase + wm * 32 + mt * 16 + r;
            float g0 = g_gate[rg], g1v = g_gate[rg + 8];
            const float* xa = aux + (size_t)rg * D_ + cb;
            float* o = dst + (size_t)rg * D_ + cb;
            #pragma unroll
            for (int j = 0; j < 8; j++) {
                float2 x0 = *(const float2*)(xa + j*8);
                float2 x1 = *(const float2*)(xa + 8*D_ + j*8);
                float2 y0 = make_float2(x0.x + acc[mt][j][0]*g0, x0.y + acc[mt][j][1]*g0);
                float2 y1 = make_float2(x1.x + acc[mt][j][2]*g1v, x1.y + acc[mt][j][3]*g1v);
                *(float2*)(o + j*8) = y0;
                *(float2*)(o + 8*D_ + j*8) = y1;
                ps[j][0] += y0.x + y1.x;
                ps[j][1] += y0.y + y1.y;
            }
        }
        #pragma unroll
        for (int j = 0; j < 8; j++) {
            #pragma unroll
            for (int off = 4; off < 32; off <<= 1) {
                ps[j][0] += __shfl_xor_sync(0xffffffffu, ps[j][0], off);
                ps[j][1] += __shfl_xor_sync(0xffffffffu, ps[j][1], off);
            }
        }
        __syncthreads();
        float* pb = (float*)&As[0][0];
        if (lane < 4) {
            #pragma unroll
            for (int j = 0; j < 8; j++) {
                pb[wm*128 + wn*64 + j*8 + 2*q]     = ps[j][0];
                pb[wm*128 + wn*64 + j*8 + 2*q + 1] = ps[j][1];
            }
        }
        __syncthreads();
        if (tid < 128) {
            float s = pb[tid] + pb[128 + tid] + pb[256 + tid] + pb[384 + tid];
            int ttile = blockIdx.y & 3;
            g_poolp[((size_t)(b*N_+n)*4 + ttile)*512 + n0 + tid] = s;
        }
    } else if (MODE == 3) {
        __half* dst = (__half*)dstv;
        constexpr float ISQ2 = 0.70710678118654752f;
        int cb = n0 + wn * 64 + 2*q;
        #pragma unroll
        for (int mt = 0; mt < 2; mt++) {
            int rg = rbase + wm * 32 + mt * 16 + r;
            #pragma unroll
            for (int j = 0; j < 8; j++) {
                int col = cb + j * 8;
                if (col < FF_) {
                    float b0 = aux[n*FF_ + col], b1 = aux[n*FF_ + col + 1];
                    float z0 = acc[mt][j][0] + b0, z1 = acc[mt][j][1] + b1;
                    float z2 = acc[mt][j][2] + b0, z3 = acc[mt][j][3] + b1;
                    *(__half2*)(dst + (size_t)rg*FFP + col) = __floats2half2_rn(
                        0.5f*z0*(1.f + erff(z0*ISQ2)), 0.5f*z1*(1.f + erff(z1*ISQ2)));
                    *(__half2*)(dst + (size_t)(rg+8)*FFP + col) = __floats2half2_rn(
                        0.5f*z2*(1.f + erff(z2*ISQ2)), 0.5f*z3*(1.f + erff(z3*ISQ2)));
                } else if (col < FFP) {
                    *(__half2*)(dst + (size_t)rg*FFP + col) = __floats2half2_rn(0.f, 0.f);
                    *(__half2*)(dst + (size_t)(rg+8)*FFP + col) = __floats2half2_rn(0.f, 0.f);
                }
            }
        }
    } else { // MODE 4
        float* dst = (float*)dstv;
        float cm = g_commit[b * N_ + n];
        int cb = n0 + wn * 64 + 2*q;
        const float* fs = g_fsig + (size_t)(b*N_+n) * D_ + cb;
        const float* db = aux + n * D_ + cb;
        #pragma unroll
        for (int mt = 0; mt < 2; mt++) {
            int rg = rbase + wm * 32 + mt * 16 + r;
            float cg0 = cm * g_gate[rg], cg1 = cm * g_gate[rg + 8];
            float* o = dst + (size_t)rg * D_ + cb;
            #pragma unroll
            for (int j = 0; j < 8; j++) {
                float2 bb = *(const float2*)(db + j*8);
                float2 ff = *(const float2*)(fs + j*8);
                float2 x0 = *(float2*)(o + j*8);
                float2 x1 = *(float2*)(o + 8*D_ + j*8);
                x0.x += cg0*(acc[mt][j][0] + bb.x) + ff.x;
                x0.y += cg0*(acc[mt][j][1] + bb.y) + ff.y;
                x1.x += cg1*(acc[mt][j][2] + bb.x) + ff.x;
                x1.y += cg1*(acc[mt][j][3] + bb.y) + ff.y;
                *(float2*)(o + j*8) = x0;
                *(float2*)(o + 8*D_ + j*8) = x1;
            }
        }
    }
}

// ---------------- flash attention: P in registers, V via ldmatrix.trans ----------------
constexpr int AQ = 0;
constexpr int AK = 128 * 72;
constexpr int AV = AK + 3 * 64 * 72;
constexpr int ATTN_SMEM_HALVES = AV + 3 * 64 * 72;

__global__ __launch_bounds__(256)
void k_attn()
{
    extern __shared__ __half sh[];

    const int bid = blockIdx.x;
    const int qt  = bid & 3;
    const int bnh = bid >> 2;
    const int bn = bnh >> 3, h = bnh & 7;
    const __half* Qb = g_qkv + (size_t)bnh * T_ * DH_ + (size_t)qt * 128 * DH_;
    const __half* Kb = g_qkv + (size_t)ROWS * D_ + (size_t)bnh * T_ * DH_;
    const __half* Vb = g_qkv + (size_t)2 * ROWS * D_ + (size_t)bnh * T_ * DH_;

    const int tid  = threadIdx.x;
    const int wid  = tid >> 5;
    const int lane = tid & 31;
    const int q = lane & 3, r = lane >> 2;
    const int rm = wid * 16;
    const int l7 = lane & 7;
    const int ga = (lane >> 3) & 1;
    const int gb = (lane >> 4) & 1;

    const uint32_t shb = (uint32_t)__cvta_generic_to_shared(sh);
    const uint32_t qsb = shb + AQ * 2;
    const uint32_t ksb = shb + AK * 2;
    const uint32_t vsb = shb + AV * 2;

    const uint32_t aoff = (uint32_t)((rm + ga*8 + l7) * 72 + gb*8) * 2;
    uint32_t boffp[4], boffv[4];
    #pragma unroll
    for (int p = 0; p < 4; p++) {
        boffp[p] = (uint32_t)((p*16 + gb*8 + l7) * 72 + ga*8) * 2;
        boffv[p] = (uint32_t)((ga*8 + l7) * 72 + p*16 + gb*8) * 2;
    }

    #pragma unroll
    for (int l = 0; l < 4; l++) {
        int idx = tid + 256 * l;
        int row = idx >> 3, c = idx & 7;
        cpa16(qsb + (uint32_t)(row * 72 + c * 8) * 2, Qb + (size_t)row * 64 + c * 8, true);
    }
    auto stageKV = [&](int it, int buf) {
        int s0 = it * 64;
        uint32_t kb = ksb + (uint32_t)(buf * 64 * 72) * 2;
        uint32_t vb = vsb + (uint32_t)(buf * 64 * 72) * 2;
        #pragma unroll
        for (int l = 0; l < 2; l++) {
            int idx = tid + 256 * l;
            int row = idx >> 3, c = idx & 7;
            cpa16(kb + (uint32_t)(row * 72 + c * 8) * 2,
                  Kb + (size_t)(s0 + row) * 64 + c * 8, true);
            cpa16(vb + (uint32_t)(row * 72 + c * 8) * 2,
                  Vb + (size_t)(s0 + row) * 64 + c * 8, true);
        }
    };

    float o[8][4];
    #pragma unroll
    for (int j = 0; j < 8; j++)
        #pragma unroll
        for (int c = 0; c < 4; c++) o[j][c] = 0.f;
    float l0 = 0.f, l1 = 0.f;
    uint32_t qf[4][4];

    stageKV(0, 0); cpcommit();
    stageKV(1, 1); cpcommit();
    for (int it = 0; it < 8; it++) {
        const int cur = it % 3;
        if (it == 7) cpwait0(); else cpwait1();
        __syncthreads();
        if (it + 2 < 8) { stageKV(it + 2, (it + 2) % 3); cpcommit(); }
        const uint32_t kb = ksb + (uint32_t)(cur * 64 * 72) * 2;
        const uint32_t vb = vsb + (uint32_t)(cur * 64 * 72) * 2;

        if (it == 0) {
            #pragma unroll
            for (int c = 0; c < 4; c++) ldm4(qf[c], qsb + aoff + c * 32);
        }

        float s[8][4];
        #pragma unroll
        for (int j = 0; j < 8; j++)
            #pragma unroll
            for (int c = 0; c < 4; c++) s[j][c] = 0.f;
        #pragma unroll
        for (int c = 0; c < 4; c++) {
            #pragma unroll
            for (int p = 0; p < 4; p++) {
                uint32_t bf[4];
                ldm4(bf, kb + boffp[p] + c * 32);
                mma_f16(s[2*p],   qf[c], bf[0], bf[1]);
                mma_f16(s[2*p+1], qf[c], bf[2], bf[3]);
            }
        }

        #pragma unroll
        for (int c = 0; c < 4; c++) {
            float e00 = __expf(s[2*c][0]),   e01 = __expf(s[2*c][1]);
            float e02 = __expf(s[2*c][2]),   e03 = __expf(s[2*c][3]);
            float e10 = __expf(s[2*c+1][0]), e11 = __expf(s[2*c+1][1]);
            float e12 = __expf(s[2*c+1][2]), e13 = __expf(s[2*c+1][3]);
            l0 += e00 + e01 + e10 + e11;
            l1 += e02 + e03 + e12 + e13;
            uint32_t a[4];
            a[0] = h2u(__floats2half2_rn(e00, e01));
            a[1] = h2u(__floats2half2_rn(e02, e03));
            a[2] = h2u(__floats2half2_rn(e10, e11));
            a[3] = h2u(__floats2half2_rn(e12, e13));
            #pragma unroll
            for (int p = 0; p < 4; p++) {
                uint32_t bf[4];
                ldm4t(bf, vb + boffv[p] + (uint32_t)(c * 16 * 72) * 2);
                mma_f16(o[2*p],   a, bf[0], bf[1]);
                mma_f16(o[2*p+1], a, bf[2], bf[3]);
            }
        }
    }

    l0 += __shfl_xor_sync(0xffffffffu, l0, 1);
    l0 += __shfl_xor_sync(0xffffffffu, l0, 2);
    l1 += __shfl_xor_sync(0xffffffffu, l1, 1);
    l1 += __shfl_xor_sync(0xffffffffu, l1, 2);
    float i0 = 1.f / l0, i1 = 1.f / l1;
    __half* d0 = g_attn + ((size_t)bn * T_ + qt * 128 + rm + r) * D_ + h * DH_ + 2 * q;
    __half* d1 = d0 + (size_t)8 * D_;
    #pragma unroll
    for (int j = 0; j < 8; j++) {
        *(__half2*)(d0 + j * 8) = __floats2half2_rn(o[j][0] * i0, o[j][1] * i0);
        *(__half2*)(d1 + j * 8) = __floats2half2_rn(o[j][2] * i1, o[j][3] * i1);
    }
}

// ---------------- commit + center + h_res + (cos,sin) ----------------
__global__ __launch_bounds__(128)
void k_small_a(const float* __restrict__ cw, const float* __restrict__ cb,
               const float* __restrict__ centw, const float* __restrict__ centb,
               const float* __restrict__ fiw)
{
    int bn = blockIdx.x, n = bn & (N_ - 1), tid = threadIdx.x;
    __shared__ float sp[D_];
    __shared__ float sc[D_];
    __shared__ float red[4];

    float4 p4 = make_float4(0.f, 0.f, 0.f, 0.f);
    #pragma unroll
    for (int c = 0; c < 4; c++) {
        float4 v = ((const float4*)g_poolp)[(bn * 4 + c) * 128 + tid];
        p4.x += v.x; p4.y += v.y; p4.z += v.z; p4.w += v.w;
    }
    p4.x *= (1.f/512.f); p4.y *= (1.f/512.f); p4.z *= (1.f/512.f); p4.w *= (1.f/512.f);
    ((float4*)sp)[tid] = p4;
    float4 w4 = ((const float4*)(cw + n * D_))[tid];
    float loc = p4.x*w4.x + p4.y*w4.y + p4.z*w4.z + p4.w*w4.w;
    #pragma unroll
    for (int off = 16; off; off >>= 1) loc += __shfl_down_sync(0xffffffffu, loc, off);
    if ((tid & 31) == 0) red[tid >> 5] = loc;
    __syncthreads();
    if (tid == 0) {
        float tot = red[0] + red[1] + red[2] + red[3] + cb[n];
        g_commit[bn] = 1.f / (1.f + expf(-tot));
    }

    float4 acc = make_float4(0.f, 0.f, 0.f, 0.f);
    const float4* cwp = (const float4*)(centw + (size_t)n * D_ * D_);
    for (int d = 0; d < D_; d++) {
        float pd = sp[d];
        float4 w = cwp[d * 128 + tid];
        acc.x = fmaf(pd, w.x, acc.x);
        acc.y = fmaf(pd, w.y, acc.y);
        acc.z = fmaf(pd, w.z, acc.z);
        acc.w = fmaf(pd, w.w, acc.w);
    }
    float4 cbv = ((const float4*)(centb + n * D_))[tid];
    acc.x = tanhf(acc.x + cbv.x);
    acc.y = tanhf(acc.y + cbv.y);
    acc.z = tanhf(acc.z + cbv.z);
    acc.w = tanhf(acc.w + cbv.w);
    ((float4*)sc)[tid] = acc;
    __syncthreads();

    float4 hr = make_float4(0.f, 0.f, 0.f, 0.f);
    const float4* fip = (const float4*)fiw;
    for (int d = 0; d < D_; d++) {
        float cd = sc[d];
        float4 w = fip[d * 128 + tid];
        hr.x = fmaf(cd, w.x, hr.x);
        hr.y = fmaf(cd, w.y, hr.y);
        hr.z = fmaf(cd, w.z, hr.z);
        hr.w = fmaf(cd, w.w, hr.w);
    }
    ((float4*)g_hres)[bn * 128 + tid] = hr;

    float rex = hr.x + 1e-8f, imx = hr.y + 1e-8f;
    float rr = fmaxf(sqrtf(rex*rex + imx*imx), 1e-30f);
    g_cs_c[bn * 256 + tid * 2]     = rex / rr;
    g_cs_s[bn * 256 + tid * 2]     = imx / rr;
    float rez = hr.z + 1e-8f, imw = hr.w + 1e-8f;
    rr = fmaxf(sqrtf(rez*rez + imw*imw), 1e-30f);
    g_cs_c[bn * 256 + tid * 2 + 1] = rez / rr;
    g_cs_s[bn * 256 + tid * 2 + 1] = imw / rr;
}

// ---------------- resonance gram matrix ----------------
__global__ __launch_bounds__(256)
void k_racc()
{
    __shared__ float cc[N_][257];
    __shared__ float sn[N_][257];
    int b = blockIdx.x, tid = threadIdx.x;
    #pragma unroll
    for (int i = 0; i < 16; i++) {
        int idx = tid + 256 * i;
        int nn = idx >> 8, p = idx & 255;
        cc[nn][p] = g_cs_c[b * 4096 + idx];
        sn[nn][p] = g_cs_s[b * 4096 + idx];
    }
    __syncthreads();
    int mrow = tid >> 4, ncol = tid & 15;
    float acc = 0.f;
    for (int p = 0; p < 256; p++)
        acc += cc[mrow][p] * cc[ncol][p] + sn[mrow][p] * sn[ncol][p];
    g_racc[b * 256 + tid] = acc * (1.f / 256.f);
}

// ---------------- recv + field_signal ----------------
__global__ __launch_bounds__(128)
void k_fieldsig(const float* __restrict__ fow, const float* __restrict__ condp)
{
    int b = blockIdx.x >> 4, mm = blockIdx.x & 15, tid = threadIdx.x;
    __shared__ float rv[D_];
    __shared__ float wgt[N_];
    if (tid < 16) wgt[tid] = g_racc[b * 256 + mm * 16 + tid] * g_commit[b * 16 + tid];
    __syncthreads();
    float4 acc = make_float4(0.f, 0.f, 0.f, 0.f);
    const float4* hp = (const float4*)g_hres;
    #pragma unroll
    for (int n2 = 0; n2 < 16; n2++) {
        float w = wgt[n2];
        float4 h4 = hp[(b * 16 + n2) * 128 + tid];
        acc.x = fmaf(w, h4.x, acc.x);
        acc.y = fmaf(w, h4.y, acc.y);
        acc.z = fmaf(w, h4.z, acc.z);
        acc.w = fmaf(w, h4.w, acc.w);
    }
    float cond = condp[0];
    acc.x *= cond; acc.y *= cond; acc.z *= cond; acc.w *= cond;
    ((float4*)rv)[tid] = acc;
    __syncthreads();
    float4 fs = make_float4(0.f, 0.f, 0.f, 0.f);
    const float4* fp = (const float4*)fow;
    for (int d = 0; d < D_; d++) {
        float rd = rv[d];
        float4 w = fp[d * 128 + tid];
        fs.x = fmaf(rd, w.x, fs.x);
        fs.y = fmaf(rd, w.y, fs.y);
        fs.z = fmaf(rd, w.z, fs.z);
        fs.w = fmaf(rd, w.w, fs.w);
    }
    ((float4*)g_fsig)[blockIdx.x * 128 + tid] = fs;
}

// ---------------- launch ----------------
extern "C" void kernel_launch(void* const* d_in, const int* in_sizes, int n_in,
                              void* d_out, int out_size)
{
    const float* x        = (const float*)d_in[0];
    const float* gate_w   = (const float*)d_in[1];
    const float* gate_b   = (const float*)d_in[2];
    const float* ln1_g    = (const float*)d_in[3];
    const float* ln1_b    = (const float*)d_in[4];
    const float* wq       = (const float*)d_in[5];
    const float* wk       = (const float*)d_in[6];
    const float* wv       = (const float*)d_in[7];
    const float* wo       = (const float*)d_in[8];
    const float* phase    = (const float*)d_in[9];
    const float* ln2_g    = (const float*)d_in[10];
    const float* ln2_b    = (const float*)d_in[11];
    const float* up_w     = (const float*)d_in[12];
    const float* up_b     = (const float*)d_in[13];
    const float* down_w   = (const float*)d_in[14];
    const float* down_b   = (const float*)d_in[15];
    const float* commit_w = (const float*)d_in[16];
    const float* commit_b = (const float*)d_in[17];
    const float* center_w = (const float*)d_in[18];
    const float* center_b = (const float*)d_in[19];
    const float* fiw      = (const float*)d_in[20];
    const float* fow      = (const float*)d_in[21];
    const float* cond     = (const float*)d_in[22];
    float* out = (float*)d_out;

    __half *p_h, *p_qkv, *p_attn, *p_up, *p_wTall, *p_upT, *p_dnT;
    cudaGetSymbolAddress((void**)&p_h,     g_h);
    cudaGetSymbolAddress((void**)&p_qkv,   g_qkv);
    cudaGetSymbolAddress((void**)&p_attn,  g_attn);
    cudaGetSymbolAddress((void**)&p_up,    g_up);
    cudaGetSymbolAddress((void**)&p_wTall, g_wTall);
    cudaGetSymbolAddress((void**)&p_upT,   g_upT);
    cudaGetSymbolAddress((void**)&p_dnT,   g_dnT);
    const size_t WSZ = (size_t)N_ * D_ * D_;

    cudaFuncSetAttribute(k_attn, cudaFuncAttributeMaxDynamicSharedMemorySize,
                         ATTN_SMEM_HALVES * 2);

    // 0. weight prep
    k_wt4<<<dim3(16, 16, 64), 256>>>(wq, wk, wv, wo);
    k_wt<<<dim3(26, 16, 16), 256>>>(up_w,   p_upT, 512, 828, 512);
    k_wt<<<dim3(16, 26, 16), 256>>>(down_w, p_dnT, 828, 512, 832);

    // 1. gate + LN1
    k_ln<1><<<ROWS / 16, 256>>>(x, ln1_g, ln1_b, gate_w, gate_b);

    // 2. Q+K+V merged projection
    k_gemm<512, 512, 0><<<dim3(4, 8, 48), 256>>>(p_h, p_wTall, p_qkv, phase);

    // 3. attention
    k_attn<<<1024, 256, ATTN_SMEM_HALVES * 2>>>();

    // 4. x1 = x + (attn@wo)*gate -> out  (+ fused pooling partials)
    k_gemm<512, 512, 2><<<dim3(4, 8, 16), 256>>>(p_attn, p_wTall + 3*WSZ, out, x);

    // 5. small chain
    k_small_a<<<32, 128>>>(commit_w, commit_b, center_w, center_b, fiw);
    k_racc<<<2, 256>>>();
    k_fieldsig<<<32, 128>>>(fow, cond);

    // 6. FFN + final fold
    k_ln<0><<<ROWS / 16, 256>>>(out, ln2_g, ln2_b, nullptr, nullptr);
    k_gemm<512, 828, 3><<<dim3(7, 8, 16), 256>>>(p_h, p_upT, p_up, up_b);
    k_gemm<832, 512, 4><<<dim3(4, 8, 16), 256>>>(p_up, p_dnT, out, down_b);
}